// round 1
// baseline (speedup 1.0000x reference)
#include <cuda_runtime.h>
#include <cuda_bf16.h>

// Problem constants
#define NTOK      8192          // 4*2048 tokens
#define DMODEL    1024
#define NEXP      8
#define DFFN      2048
#define EF        (NEXP*DFFN)   // 16384

// Tiling
#define BM        128
#define BN        128
#define BK        16
#define MAXTILES  136           // 16384/128 + 8 experts worst-case padding
#define MAXROWS   (MAXTILES*BM) // 17408

// ---------------- device scratch (no runtime allocation allowed) -------------
__device__ int   g_expert[NTOK*2];
__device__ float g_gatew [NTOK*2];
__device__ int   g_cnt   [NEXP];
__device__ int   g_cursor[NEXP];
__device__ int   g_off   [NEXP];
__device__ int   g_tile_expert[MAXTILES];
__device__ int   g_rowtok[MAXROWS];
__device__ float g_roww  [MAXROWS];
__device__ float g_H[(size_t)MAXROWS * DFFN];   // ~142 MB intermediate

// ---------------- K0: zero out + reset bookkeeping ---------------------------
__global__ void init_kernel(float* __restrict__ out) {
    const size_t n = (size_t)NTOK * DMODEL;
    size_t stride = (size_t)gridDim.x * blockDim.x;
    for (size_t i = (size_t)blockIdx.x * blockDim.x + threadIdx.x; i < n; i += stride)
        out[i] = 0.0f;
    for (size_t i = (size_t)blockIdx.x * blockDim.x + threadIdx.x; i < MAXROWS; i += stride)
        g_rowtok[i] = -1;
    if (blockIdx.x == 0 && threadIdx.x < NEXP) {
        g_cnt[threadIdx.x] = 0;
        g_cursor[threadIdx.x] = 0;
    }
}

// ---------------- K1: router (one warp per token) ----------------------------
__global__ __launch_bounds__(256) void router_kernel(const float* __restrict__ x,
                                                     const float* __restrict__ rw) {
    int warp = (blockIdx.x * blockDim.x + threadIdx.x) >> 5;
    int lane = threadIdx.x & 31;
    if (warp >= NTOK) return;

    const float* xr = x + (size_t)warp * DMODEL;
    float xv[32];
#pragma unroll
    for (int i = 0; i < 32; i++) xv[i] = xr[i * 32 + lane];

    float logit[NEXP];
#pragma unroll
    for (int e = 0; e < NEXP; e++) {
        const float* wr = rw + e * DMODEL;
        float s = 0.0f;
#pragma unroll
        for (int i = 0; i < 32; i++) s = fmaf(xv[i], wr[i * 32 + lane], s);
#pragma unroll
        for (int o = 16; o > 0; o >>= 1) s += __shfl_xor_sync(0xffffffffu, s, o);
        logit[e] = s;
    }

    if (lane == 0) {
        int i0 = 0;
#pragma unroll
        for (int e = 1; e < NEXP; e++) if (logit[e] > logit[i0]) i0 = e;
        int i1 = -1;
#pragma unroll
        for (int e = 0; e < NEXP; e++) {
            if (e == i0) continue;
            if (i1 < 0 || logit[e] > logit[i1]) i1 = e;
        }
        // renormalized top-2 softmax weights: w0 = 1/(1+e^{l1-l0})
        float t  = expf(logit[i1] - logit[i0]);
        float w0 = 1.0f / (1.0f + t);
        float w1 = t * w0;
        g_expert[2 * warp]     = i0;  g_gatew[2 * warp]     = w0;
        g_expert[2 * warp + 1] = i1;  g_gatew[2 * warp + 1] = w1;
        atomicAdd(&g_cnt[i0], 1);
        atomicAdd(&g_cnt[i1], 1);
    }
}

// ---------------- K2: tiny serial setup (offsets padded to BM, tile map) -----
__global__ void setup_kernel() {
    int row = 0, tile = 0;
    for (int e = 0; e < NEXP; e++) {
        g_off[e] = row;
        g_cursor[e] = 0;
        int nt = (g_cnt[e] + BM - 1) / BM;
        for (int i = 0; i < nt; i++) g_tile_expert[tile++] = e;
        row += nt * BM;
    }
    for (; tile < MAXTILES; ++tile) g_tile_expert[tile] = -1;
}

// ---------------- K3: scatter token assignments into expert segments ---------
__global__ void scatter_kernel() {
    int i = blockIdx.x * blockDim.x + threadIdx.x;
    if (i >= NTOK * 2) return;
    int e = g_expert[i];
    int pos = g_off[e] + atomicAdd(&g_cursor[e], 1);
    g_rowtok[pos] = i >> 1;
    g_roww[pos]   = g_gatew[i];
}

// ---------------- K4: grouped GEMM1 + exact GELU -> g_H ----------------------
__global__ __launch_bounds__(256) void gemm1_kernel(const float* __restrict__ x,
                                                    const float* __restrict__ w1) {
    int e = g_tile_expert[blockIdx.x];
    if (e < 0) return;

    __shared__ int   stok[BM];
    __shared__ float sA[BK][BM];
    __shared__ float sB[BK][BN];

    int tid = threadIdx.x;
    int r0 = blockIdx.x * BM;
    int nbase = blockIdx.y * BN;
    if (tid < BM) stok[tid] = g_rowtok[r0 + tid];
    __syncthreads();

    int tx = tid & 15, ty = tid >> 4;
    float acc[8][8] = {};

    int am = tid >> 2;           // 0..63 (A row, +64 in rep 1)
    int ak = (tid & 3) * 4;      // 0,4,8,12
    int bk = tid >> 5;           // 0..7  (B k-row, +8 in rep 1)
    int bn = (tid & 31) * 4;     // 0..124
    const float* w1base = w1 + (size_t)e * DFFN + nbase;

    for (int kk = 0; kk < DMODEL; kk += BK) {
#pragma unroll
        for (int rep = 0; rep < 2; rep++) {
            int m = am + rep * 64;
            int tok = stok[m];
            float4 v = make_float4(0.f, 0.f, 0.f, 0.f);
            if (tok >= 0) v = *(const float4*)(x + (size_t)tok * DMODEL + kk + ak);
            sA[ak + 0][m] = v.x; sA[ak + 1][m] = v.y;
            sA[ak + 2][m] = v.z; sA[ak + 3][m] = v.w;

            int k = bk + rep * 8;
            float4 bv = *(const float4*)(w1base + (size_t)(kk + k) * EF + bn);
            *(float4*)&sB[k][bn] = bv;
        }
        __syncthreads();
#pragma unroll
        for (int k = 0; k < BK; k++) {
            float a[8], b[8];
#pragma unroll
            for (int i = 0; i < 8; i++) a[i] = sA[k][ty * 8 + i];
#pragma unroll
            for (int j = 0; j < 8; j++) b[j] = sB[k][tx * 8 + j];
#pragma unroll
            for (int i = 0; i < 8; i++)
#pragma unroll
                for (int j = 0; j < 8; j++)
                    acc[i][j] = fmaf(a[i], b[j], acc[i][j]);
        }
        __syncthreads();
    }

    // exact GELU epilogue -> H
#pragma unroll
    for (int i = 0; i < 8; i++) {
        int gr = r0 + ty * 8 + i;
        float* hrow = g_H + (size_t)gr * DFFN + nbase + tx * 8;
#pragma unroll
        for (int j = 0; j < 8; j++) {
            float v = acc[i][j];
            hrow[j] = 0.5f * v * (1.0f + erff(v * 0.70710678118654752f));
        }
    }
}

// ---------------- K5: grouped GEMM2 + weighted atomic scatter into out -------
__global__ __launch_bounds__(256) void gemm2_kernel(const float* __restrict__ w2,
                                                    float* __restrict__ out) {
    int e = g_tile_expert[blockIdx.x];
    if (e < 0) return;

    __shared__ int   stok[BM];
    __shared__ float srw [BM];
    __shared__ float sA[BK][BM];
    __shared__ float sB[BK][BN];

    int tid = threadIdx.x;
    int r0 = blockIdx.x * BM;
    int nbase = blockIdx.y * BN;
    if (tid < BM) { stok[tid] = g_rowtok[r0 + tid]; srw[tid] = g_roww[r0 + tid]; }
    __syncthreads();

    int tx = tid & 15, ty = tid >> 4;
    float acc[8][8] = {};

    int am = tid >> 2;
    int ak = (tid & 3) * 4;
    int bk = tid >> 5;
    int bn = (tid & 31) * 4;
    const float* w2base = w2 + (size_t)e * DFFN * DMODEL + nbase;

    for (int kk = 0; kk < DFFN; kk += BK) {
#pragma unroll
        for (int rep = 0; rep < 2; rep++) {
            int m = am + rep * 64;
            float4 v = *(const float4*)(g_H + (size_t)(r0 + m) * DFFN + kk + ak);
            sA[ak + 0][m] = v.x; sA[ak + 1][m] = v.y;
            sA[ak + 2][m] = v.z; sA[ak + 3][m] = v.w;

            int k = bk + rep * 8;
            float4 bv = *(const float4*)(w2base + (size_t)(kk + k) * DMODEL + bn);
            *(float4*)&sB[k][bn] = bv;
        }
        __syncthreads();
#pragma unroll
        for (int k = 0; k < BK; k++) {
            float a[8], b[8];
#pragma unroll
            for (int i = 0; i < 8; i++) a[i] = sA[k][ty * 8 + i];
#pragma unroll
            for (int j = 0; j < 8; j++) b[j] = sB[k][tx * 8 + j];
#pragma unroll
            for (int i = 0; i < 8; i++)
#pragma unroll
                for (int j = 0; j < 8; j++)
                    acc[i][j] = fmaf(a[i], b[j], acc[i][j]);
        }
        __syncthreads();
    }

    // weighted scatter-add: each token gets exactly 2 commutative fp32 adds
#pragma unroll
    for (int i = 0; i < 8; i++) {
        int m = ty * 8 + i;
        int tok = stok[m];
        if (tok < 0) continue;
        float w = srw[m];
        float* orow = out + (size_t)tok * DMODEL + nbase + tx * 8;
#pragma unroll
        for (int j = 0; j < 8; j++)
            atomicAdd(&orow[j], w * acc[i][j]);
    }
}

// ---------------- launch ------------------------------------------------------
extern "C" void kernel_launch(void* const* d_in, const int* in_sizes, int n_in,
                              void* d_out, int out_size) {
    const float* x  = (const float*)d_in[0];   // [8192, 1024]
    const float* rw = (const float*)d_in[1];   // [8, 1024]
    const float* w1 = (const float*)d_in[2];   // [1024, 16384]
    const float* w2 = (const float*)d_in[3];   // [16384, 1024]
    float* out = (float*)d_out;                // [8192, 1024]

    init_kernel   <<<2048, 256>>>(out);
    router_kernel <<<NTOK / 8, 256>>>(x, rw);              // 8 warps/block
    setup_kernel  <<<1, 1>>>();
    scatter_kernel<<<(NTOK * 2 + 255) / 256, 256>>>();
    gemm1_kernel  <<<dim3(MAXTILES, DFFN / BN), 256>>>(x, w1);
    gemm2_kernel  <<<dim3(MAXTILES, DMODEL / BN), 256>>>(w2, out);
}

// round 2
// speedup vs baseline: 1.0009x; 1.0009x over previous
#include <cuda_runtime.h>
#include <cuda_bf16.h>

// Problem constants
#define NTOK      8192          // 4*2048 tokens
#define DMODEL    1024
#define NEXP      8
#define DFFN      2048
#define EF        (NEXP*DFFN)   // 16384

// Tiling
#define BM        128
#define BN        128
#define BK        16
#define MAXTILES  136           // 16384/128 + 8 experts worst-case padding
#define MAXROWS   (MAXTILES*BM) // 17408

// ---------------- device scratch (no runtime allocation allowed) -------------
__device__ int   g_expert[NTOK*2];
__device__ float g_gatew [NTOK*2];
__device__ int   g_cnt   [NEXP];
__device__ int   g_cursor[NEXP];
__device__ int   g_off   [NEXP];
__device__ int   g_tile_expert[MAXTILES];
__device__ int   g_rowtok[MAXROWS];
__device__ float g_roww  [MAXROWS];
__device__ float g_H[(size_t)MAXROWS * DFFN];   // ~142 MB intermediate

// ---------------- K0: zero out + reset bookkeeping ---------------------------
__global__ void init_kernel(float* __restrict__ out) {
    const size_t n = (size_t)NTOK * DMODEL;
    size_t stride = (size_t)gridDim.x * blockDim.x;
    for (size_t i = (size_t)blockIdx.x * blockDim.x + threadIdx.x; i < n; i += stride)
        out[i] = 0.0f;
    for (size_t i = (size_t)blockIdx.x * blockDim.x + threadIdx.x; i < MAXROWS; i += stride)
        g_rowtok[i] = -1;
    if (blockIdx.x == 0 && threadIdx.x < NEXP) {
        g_cnt[threadIdx.x] = 0;
        g_cursor[threadIdx.x] = 0;
    }
}

// ---------------- K1: router (one warp per token) ----------------------------
__global__ __launch_bounds__(256) void router_kernel(const float* __restrict__ x,
                                                     const float* __restrict__ rw) {
    int warp = (blockIdx.x * blockDim.x + threadIdx.x) >> 5;
    int lane = threadIdx.x & 31;
    if (warp >= NTOK) return;

    const float* xr = x + (size_t)warp * DMODEL;
    float xv[32];
#pragma unroll
    for (int i = 0; i < 32; i++) xv[i] = xr[i * 32 + lane];

    float logit[NEXP];
#pragma unroll
    for (int e = 0; e < NEXP; e++) {
        const float* wr = rw + e * DMODEL;
        float s = 0.0f;
#pragma unroll
        for (int i = 0; i < 32; i++) s = fmaf(xv[i], wr[i * 32 + lane], s);
#pragma unroll
        for (int o = 16; o > 0; o >>= 1) s += __shfl_xor_sync(0xffffffffu, s, o);
        logit[e] = s;
    }

    if (lane == 0) {
        int i0 = 0;
#pragma unroll
        for (int e = 1; e < NEXP; e++) if (logit[e] > logit[i0]) i0 = e;
        int i1 = -1;
#pragma unroll
        for (int e = 0; e < NEXP; e++) {
            if (e == i0) continue;
            if (i1 < 0 || logit[e] > logit[i1]) i1 = e;
        }
        // renormalized top-2 softmax weights: w0 = 1/(1+e^{l1-l0})
        float t  = expf(logit[i1] - logit[i0]);
        float w0 = 1.0f / (1.0f + t);
        float w1 = t * w0;
        g_expert[2 * warp]     = i0;  g_gatew[2 * warp]     = w0;
        g_expert[2 * warp + 1] = i1;  g_gatew[2 * warp + 1] = w1;
        atomicAdd(&g_cnt[i0], 1);
        atomicAdd(&g_cnt[i1], 1);
    }
}

// ---------------- K2: tiny serial setup (offsets padded to BM, tile map) -----
__global__ void setup_kernel() {
    int row = 0, tile = 0;
    for (int e = 0; e < NEXP; e++) {
        g_off[e] = row;
        g_cursor[e] = 0;
        int nt = (g_cnt[e] + BM - 1) / BM;
        for (int i = 0; i < nt; i++) g_tile_expert[tile++] = e;
        row += nt * BM;
    }
    for (; tile < MAXTILES; ++tile) g_tile_expert[tile] = -1;
}

// ---------------- K3: scatter token assignments into expert segments ---------
__global__ void scatter_kernel() {
    int i = blockIdx.x * blockDim.x + threadIdx.x;
    if (i >= NTOK * 2) return;
    int e = g_expert[i];
    int pos = g_off[e] + atomicAdd(&g_cursor[e], 1);
    g_rowtok[pos] = i >> 1;
    g_roww[pos]   = g_gatew[i];
}

// ---------------- K4: grouped GEMM1 + exact GELU -> g_H ----------------------
__global__ __launch_bounds__(256) void gemm1_kernel(const float* __restrict__ x,
                                                    const float* __restrict__ w1) {
    int e = g_tile_expert[blockIdx.x];
    if (e < 0) return;

    __shared__ int   stok[BM];
    __shared__ float sA[BK][BM];
    __shared__ float sB[BK][BN];

    int tid = threadIdx.x;
    int r0 = blockIdx.x * BM;
    int nbase = blockIdx.y * BN;
    if (tid < BM) stok[tid] = g_rowtok[r0 + tid];
    __syncthreads();

    int tx = tid & 15, ty = tid >> 4;
    float acc[8][8] = {};

    int am = tid >> 2;           // 0..63 (A row, +64 in rep 1)
    int ak = (tid & 3) * 4;      // 0,4,8,12
    int bk = tid >> 5;           // 0..7  (B k-row, +8 in rep 1)
    int bn = (tid & 31) * 4;     // 0..124
    const float* w1base = w1 + (size_t)e * DFFN + nbase;

    for (int kk = 0; kk < DMODEL; kk += BK) {
#pragma unroll
        for (int rep = 0; rep < 2; rep++) {
            int m = am + rep * 64;
            int tok = stok[m];
            float4 v = make_float4(0.f, 0.f, 0.f, 0.f);
            if (tok >= 0) v = *(const float4*)(x + (size_t)tok * DMODEL + kk + ak);
            sA[ak + 0][m] = v.x; sA[ak + 1][m] = v.y;
            sA[ak + 2][m] = v.z; sA[ak + 3][m] = v.w;

            int k = bk + rep * 8;
            float4 bv = *(const float4*)(w1base + (size_t)(kk + k) * EF + bn);
            *(float4*)&sB[k][bn] = bv;
        }
        __syncthreads();
#pragma unroll
        for (int k = 0; k < BK; k++) {
            float a[8], b[8];
#pragma unroll
            for (int i = 0; i < 8; i++) a[i] = sA[k][ty * 8 + i];
#pragma unroll
            for (int j = 0; j < 8; j++) b[j] = sB[k][tx * 8 + j];
#pragma unroll
            for (int i = 0; i < 8; i++)
#pragma unroll
                for (int j = 0; j < 8; j++)
                    acc[i][j] = fmaf(a[i], b[j], acc[i][j]);
        }
        __syncthreads();
    }

    // exact GELU epilogue -> H
#pragma unroll
    for (int i = 0; i < 8; i++) {
        int gr = r0 + ty * 8 + i;
        float* hrow = g_H + (size_t)gr * DFFN + nbase + tx * 8;
#pragma unroll
        for (int j = 0; j < 8; j++) {
            float v = acc[i][j];
            hrow[j] = 0.5f * v * (1.0f + erff(v * 0.70710678118654752f));
        }
    }
}

// ---------------- K5: grouped GEMM2 + weighted atomic scatter into out -------
__global__ __launch_bounds__(256) void gemm2_kernel(const float* __restrict__ w2,
                                                    float* __restrict__ out) {
    int e = g_tile_expert[blockIdx.x];
    if (e < 0) return;

    __shared__ int   stok[BM];
    __shared__ float srw [BM];
    __shared__ float sA[BK][BM];
    __shared__ float sB[BK][BN];

    int tid = threadIdx.x;
    int r0 = blockIdx.x * BM;
    int nbase = blockIdx.y * BN;
    if (tid < BM) { stok[tid] = g_rowtok[r0 + tid]; srw[tid] = g_roww[r0 + tid]; }
    __syncthreads();

    int tx = tid & 15, ty = tid >> 4;
    float acc[8][8] = {};

    int am = tid >> 2;
    int ak = (tid & 3) * 4;
    int bk = tid >> 5;
    int bn = (tid & 31) * 4;
    const float* w2base = w2 + (size_t)e * DFFN * DMODEL + nbase;

    for (int kk = 0; kk < DFFN; kk += BK) {
#pragma unroll
        for (int rep = 0; rep < 2; rep++) {
            int m = am + rep * 64;
            float4 v = *(const float4*)(g_H + (size_t)(r0 + m) * DFFN + kk + ak);
            sA[ak + 0][m] = v.x; sA[ak + 1][m] = v.y;
            sA[ak + 2][m] = v.z; sA[ak + 3][m] = v.w;

            int k = bk + rep * 8;
            float4 bv = *(const float4*)(w2base + (size_t)(kk + k) * DMODEL + bn);
            *(float4*)&sB[k][bn] = bv;
        }
        __syncthreads();
#pragma unroll
        for (int k = 0; k < BK; k++) {
            float a[8], b[8];
#pragma unroll
            for (int i = 0; i < 8; i++) a[i] = sA[k][ty * 8 + i];
#pragma unroll
            for (int j = 0; j < 8; j++) b[j] = sB[k][tx * 8 + j];
#pragma unroll
            for (int i = 0; i < 8; i++)
#pragma unroll
                for (int j = 0; j < 8; j++)
                    acc[i][j] = fmaf(a[i], b[j], acc[i][j]);
        }
        __syncthreads();
    }

    // weighted scatter-add: each token gets exactly 2 commutative fp32 adds
#pragma unroll
    for (int i = 0; i < 8; i++) {
        int m = ty * 8 + i;
        int tok = stok[m];
        if (tok < 0) continue;
        float w = srw[m];
        float* orow = out + (size_t)tok * DMODEL + nbase + tx * 8;
#pragma unroll
        for (int j = 0; j < 8; j++)
            atomicAdd(&orow[j], w * acc[i][j]);
    }
}

// ---------------- launch ------------------------------------------------------
extern "C" void kernel_launch(void* const* d_in, const int* in_sizes, int n_in,
                              void* d_out, int out_size) {
    const float* x  = (const float*)d_in[0];   // [8192, 1024]
    const float* rw = (const float*)d_in[1];   // [8, 1024]
    const float* w1 = (const float*)d_in[2];   // [1024, 16384]
    const float* w2 = (const float*)d_in[3];   // [16384, 1024]
    float* out = (float*)d_out;                // [8192, 1024]

    init_kernel   <<<2048, 256>>>(out);
    router_kernel <<<NTOK / 8, 256>>>(x, rw);              // 8 warps/block
    setup_kernel  <<<1, 1>>>();
    scatter_kernel<<<(NTOK * 2 + 255) / 256, 256>>>();
    gemm1_kernel  <<<dim3(MAXTILES, DFFN / BN), 256>>>(x, w1);
    gemm2_kernel  <<<dim3(MAXTILES, DMODEL / BN), 256>>>(w2, out);
}